// round 11
// baseline (speedup 1.0000x reference)
#include <cuda_runtime.h>
#include <cuda_bf16.h>

#define FULLMASK 0xffffffffu
#define MAXL 32

// HierarchicalSoftmax. TWO samples per warp ("fewer, fatter warps"):
// halves chip-wide warp count (less cross-warp L1tex queue contention per the
// B300 spread model) while doubling each warp's independent in-flight load
// window and amortizing prologue/epilogue fixed costs over 2 samples.
// Per sample: two 16-step chunks, each a batched W-row load burst + 16-acc
// register butterfly that transposes step-sums onto lanes (lane l ends with
// the dot product of step l).
// Path validity from data: Huffman root id 0 is the LAST valid entry of every
// path; padding is also 0 -> active[l] = (l<L) && (l==0 || node[l-1]!=0).

__device__ __forceinline__ void hs_loads16(const float4* __restrict__ W4,
                                           unsigned am, int base, int my_node,
                                           int lane, float (&acc)[16],
                                           float4 e0, float4 e1, float4 e2, float4 e3)
{
    #pragma unroll
    for (int i = 0; i < 16; ++i) {
        float s = 0.0f;
        if ((am >> (base + i)) & 1u) {               // warp-uniform (prefix mask)
            int node = __shfl_sync(FULLMASK, my_node, base + i);
            const float4* w4 = W4 + (size_t)node * 128;
            float4 w0 = w4[lane +  0];
            float4 w1 = w4[lane + 32];
            float4 w2 = w4[lane + 64];
            float4 w3 = w4[lane + 96];
            s = e0.x * w0.x;
            s = fmaf(e0.y, w0.y, s); s = fmaf(e0.z, w0.z, s); s = fmaf(e0.w, w0.w, s);
            s = fmaf(e1.x, w1.x, s); s = fmaf(e1.y, w1.y, s);
            s = fmaf(e1.z, w1.z, s); s = fmaf(e1.w, w1.w, s);
            s = fmaf(e2.x, w2.x, s); s = fmaf(e2.y, w2.y, s);
            s = fmaf(e2.z, w2.z, s); s = fmaf(e2.w, w2.w, s);
            s = fmaf(e3.x, w3.x, s); s = fmaf(e3.y, w3.y, s);
            s = fmaf(e3.z, w3.z, s); s = fmaf(e3.w, w3.w, s);
        }
        acc[i] = s;
    }
}

__device__ __forceinline__ float hs_butterfly16r(float (&acc)[16], int lane)
{
    // Strides 8..1 reduce within each 16-lane half; then stride-16 combine.
    // Afterwards lane l holds the full 32-lane dot of step (l & 15).
    #pragma unroll
    for (int h = 8; h >= 1; h >>= 1) {
        #pragma unroll
        for (int i = 0; i < h; ++i) {
            float v = acc[i], w = acc[i + h];
            float give = (lane & h) ? v : w;
            float got  = __shfl_xor_sync(FULLMASK, give, h);
            acc[i] = ((lane & h) ? w : v) + got;
        }
    }
    return acc[0] + __shfl_xor_sync(FULLMASK, acc[0], 16);
}

__global__ __launch_bounds__(128, 4)
void hs512_v11_kernel(const float* __restrict__ emb,
                      const float* __restrict__ W,
                      const float* __restrict__ bias,
                      const int*   __restrict__ target,
                      const int*   __restrict__ path_nodes,
                      const int*   __restrict__ path_dirs,
                      float*       __restrict__ out,
                      int B, int L)
{
    const int D4 = 512 / 4;                                    // 128 float4 per row
    int gw   = (blockIdx.x * blockDim.x + threadIdx.x) >> 5;   // one warp = 2 samples
    int lane = threadIdx.x & 31;
    int s0 = gw * 2;
    int s1 = s0 + 1;
    if (s0 >= B) return;
    bool has1 = (s1 < B);

    const float4* W4 = reinterpret_cast<const float4*>(W);

    // ── Prologue: both embeddings + both paths' node/dir, all independent.
    const float4* ea = reinterpret_cast<const float4*>(emb) + (size_t)s0 * D4;
    float4 a0 = ea[lane +  0];
    float4 a1 = ea[lane + 32];
    float4 a2 = ea[lane + 64];
    float4 a3 = ea[lane + 96];

    float4 b0, b1, b2, b3;
    if (has1) {
        const float4* eb = reinterpret_cast<const float4*>(emb) + (size_t)s1 * D4;
        b0 = eb[lane +  0];
        b1 = eb[lane + 32];
        b2 = eb[lane + 64];
        b3 = eb[lane + 96];
    } else {
        b0 = b1 = b2 = b3 = make_float4(0.f, 0.f, 0.f, 0.f);
    }

    int t0 = __ldg(target + s0);
    int t1 = has1 ? __ldg(target + s1) : t0;
    const int* nrow0 = path_nodes + (size_t)t0 * L;
    const int* drow0 = path_dirs  + (size_t)t0 * L;
    const int* nrow1 = path_nodes + (size_t)t1 * L;
    const int* drow1 = path_dirs  + (size_t)t1 * L;

    int nodeA = (lane < L) ? __ldg(nrow0 + lane) : 0;   // lane l owns step l
    int nodeB = (lane < L) ? __ldg(nrow1 + lane) : 0;
    int dirA  = (lane < L) ? __ldg(drow0 + lane) : 0;
    int dirB  = (lane < L) ? __ldg(drow1 + lane) : 0;

    int prevA = __shfl_up_sync(FULLMASK, nodeA, 1);
    int prevB = __shfl_up_sync(FULLMASK, nodeB, 1);
    bool actA = (lane < L) && (lane == 0 || prevA != 0);
    bool actB = has1 && (lane < L) && (lane == 0 || prevB != 0);
    unsigned amA = __ballot_sync(FULLMASK, actA);
    unsigned amB = __ballot_sync(FULLMASK, actB);

    // Prefetch biases for the epilogue (independent of the heavy phase).
    float biasA = actA ? __ldg(bias + nodeA) : 0.0f;
    float biasB = actB ? __ldg(bias + nodeB) : 0.0f;

    // ── Chunk A for BOTH samples: both load bursts issued before any butterfly.
    float accA0[16], accA1[16];
    hs_loads16(W4, amA, 0, nodeA, lane, accA0, a0, a1, a2, a3);
    if (has1)
        hs_loads16(W4, amB, 0, nodeB, lane, accA1, b0, b1, b2, b3);

    float sA0 = hs_butterfly16r(accA0, lane);
    float sA1 = 0.0f;
    if (has1) sA1 = hs_butterfly16r(accA1, lane);

    // ── Chunk B (steps 16..31) for whichever sample needs it.
    unsigned hiA = amA >> 16, hiB = amB >> 16;
    float sB0 = 0.0f, sB1 = 0.0f;
    if (hiA | hiB) {
        float accB0[16], accB1[16];
        if (hiA) hs_loads16(W4, amA, 16, nodeA, lane, accB0, a0, a1, a2, a3);
        if (hiB) hs_loads16(W4, amB, 16, nodeB, lane, accB1, b0, b1, b2, b3);
        if (hiA) sB0 = hs_butterfly16r(accB0, lane);
        if (hiB) sB1 = hs_butterfly16r(accB1, lane);
    }

    // ── Epilogues: lane l holds step l's dot (chunk A for l<16, B for l>=16).
    float dv0 = (lane < 16) ? sA0 : sB0;
    float dv1 = (lane < 16) ? sA1 : sB1;

    float f0 = 1.0f, f1 = 1.0f;
    if (actA) {
        float sc = dv0 + biasA;
        float sg = dirA ? sc : -sc;
        f0 = __fdividef(1.0f, 1.0f + __expf(-sg));
    }
    if (actB) {
        float sc = dv1 + biasB;
        float sg = dirB ? sc : -sc;
        f1 = __fdividef(1.0f, 1.0f + __expf(-sg));
    }
    #pragma unroll
    for (int o = 16; o >= 1; o >>= 1) {
        f0 *= __shfl_xor_sync(FULLMASK, f0, o);
        f1 *= __shfl_xor_sync(FULLMASK, f1, o);
    }

    if (lane == 0) {
        out[s0] = f0;
        if (has1) out[s1] = f1;
    }
}

// Generic fallback (any D, any L) — shape safety, not the hot path.
__global__ __launch_bounds__(256)
void hs_generic_kernel(const float* __restrict__ emb,
                       const float* __restrict__ W,
                       const float* __restrict__ bias,
                       const int*   __restrict__ target,
                       const int*   __restrict__ path_nodes,
                       const int*   __restrict__ path_dirs,
                       float*       __restrict__ out,
                       int B, int D, int L)
{
    int gw   = (blockIdx.x * blockDim.x + threadIdx.x) >> 5;
    int lane = threadIdx.x & 31;
    if (gw >= B) return;

    const float* e = emb + (size_t)gw * D;
    int t = __ldg(target + gw);
    const int* nrow = path_nodes + (size_t)t * L;
    const int* drow = path_dirs  + (size_t)t * L;

    float prod = 1.0f;
    for (int l = 0; l < L; ++l) {
        int node = __ldg(nrow + l);
        int dir  = __ldg(drow + l);
        const float* w = W + (size_t)node * D;
        float acc = 0.0f;
        for (int d = lane; d < D; d += 32)
            acc = fmaf(e[d], w[d], acc);
        #pragma unroll
        for (int off = 16; off > 0; off >>= 1)
            acc += __shfl_xor_sync(FULLMASK, acc, off);
        float s  = acc + __ldg(bias + node);
        float sg = dir ? s : -s;
        prod *= __fdividef(1.0f, 1.0f + __expf(-sg));
        if (node == 0) break;
    }
    if (lane == 0) out[gw] = prod;
}

extern "C" void kernel_launch(void* const* d_in, const int* in_sizes, int n_in,
                              void* d_out, int out_size)
{
    const float* emb    = (const float*)d_in[0];   // [B, D] f32
    const float* W      = (const float*)d_in[1];   // [V-1, D] f32
    const float* bias   = (const float*)d_in[2];   // [V-1] f32
    const int*   target = (const int*)  d_in[3];   // [B] i32
    const int*   nodes  = (const int*)  d_in[4];   // [V, L] i32
    const int*   dirs   = (const int*)  d_in[5];   // [V, L] i32
    // d_in[6] = path_mask: unused (validity derived from node==0 sentinel)

    int B = in_sizes[3];
    int D = in_sizes[0] / B;
    int V = in_sizes[2] + 1;
    int L = in_sizes[4] / V;
    float* out = (float*)d_out;

    if (D == 512 && L <= MAXL) {
        int nwarps  = (B + 1) / 2;                 // 2 samples per warp
        int blocks  = (nwarps + 3) / 4;            // 4 warps per block
        hs512_v11_kernel<<<blocks, 128>>>(emb, W, bias, target, nodes, dirs, out, B, L);
    } else {
        int threads = 256;
        int blocks  = (B * 32 + threads - 1) / threads;
        hs_generic_kernel<<<blocks, threads>>>(emb, W, bias, target, nodes, dirs, out, B, D, L);
    }
}

// round 12
// speedup vs baseline: 1.1555x; 1.1555x over previous
#include <cuda_runtime.h>
#include <cuda_bf16.h>

#define FULLMASK 0xffffffffu
#define MAXL 32
#define HOTK 12          // W rows 0..HOTK-1 cached in smem (near-root = hot)

// HierarchicalSoftmax. One warp per sample; two 16-step chunks, each a batched
// W-row load burst + 16-acc register butterfly that transposes step-sums onto
// lanes (lane l ends with the dot product of step l).
//
// NEW (v12): Huffman node ids are assigned in merge order, so SMALL ids are the
// near-root, massively-shared rows (id 0 = root is read by every warp). Each
// block cooperatively caches W rows 0..HOTK-1 in shared memory; steps whose
// node id < HOTK read via LDS (29 cyc, conflict-free) instead of LDG (~250 cyc
// L2), removing ~25% of all LDG wavefronts from the L1tex queue.
//
// Path validity from data: Huffman root id 0 is the LAST valid entry of every
// path; padding is also 0 -> active[l] = (l<L) && (l==0 || node[l-1]!=0).

__device__ __forceinline__ float hs_dot16_hot(const float4* __restrict__ W4,
                                              const float4* __restrict__ sW,
                                              unsigned am, int base, int my_node,
                                              int lane,
                                              float4 e0, float4 e1, float4 e2, float4 e3)
{
    float acc[16];
    #pragma unroll
    for (int i = 0; i < 16; ++i) {
        float s = 0.0f;
        if ((am >> (base + i)) & 1u) {               // warp-uniform (prefix mask)
            int node = __shfl_sync(FULLMASK, my_node, base + i);
            float4 w0, w1, w2, w3;
            if (node < HOTK) {                        // warp-uniform: hot row in smem
                const float4* s4 = sW + node * 128;
                w0 = s4[lane +  0];
                w1 = s4[lane + 32];
                w2 = s4[lane + 64];
                w3 = s4[lane + 96];
            } else {
                const float4* w4 = W4 + (size_t)node * 128;
                w0 = w4[lane +  0];
                w1 = w4[lane + 32];
                w2 = w4[lane + 64];
                w3 = w4[lane + 96];
            }
            s = e0.x * w0.x;
            s = fmaf(e0.y, w0.y, s); s = fmaf(e0.z, w0.z, s); s = fmaf(e0.w, w0.w, s);
            s = fmaf(e1.x, w1.x, s); s = fmaf(e1.y, w1.y, s);
            s = fmaf(e1.z, w1.z, s); s = fmaf(e1.w, w1.w, s);
            s = fmaf(e2.x, w2.x, s); s = fmaf(e2.y, w2.y, s);
            s = fmaf(e2.z, w2.z, s); s = fmaf(e2.w, w2.w, s);
            s = fmaf(e3.x, w3.x, s); s = fmaf(e3.y, w3.y, s);
            s = fmaf(e3.z, w3.z, s); s = fmaf(e3.w, w3.w, s);
        }
        acc[i] = s;
    }
    // Butterfly: strides 8..1 reduce within each 16-lane half; afterwards lane l
    // holds the half-sum of step (l & 15). Stride-16 combine -> full dot product.
    #pragma unroll
    for (int h = 8; h >= 1; h >>= 1) {
        #pragma unroll
        for (int i = 0; i < h; ++i) {
            float v = acc[i], w = acc[i + h];
            float give = (lane & h) ? v : w;
            float got  = __shfl_xor_sync(FULLMASK, give, h);
            acc[i] = ((lane & h) ? w : v) + got;
        }
    }
    return acc[0] + __shfl_xor_sync(FULLMASK, acc[0], 16);
}

__global__ __launch_bounds__(128, 7)
void hs512_v12_kernel(const float* __restrict__ emb,
                      const float* __restrict__ W,
                      const float* __restrict__ bias,
                      const int*   __restrict__ target,
                      const int*   __restrict__ path_nodes,
                      const int*   __restrict__ path_dirs,
                      float*       __restrict__ out,
                      int B, int L)
{
    __shared__ float4 sW[HOTK * 128];                          // 24 KB hot-row cache

    const int D4 = 512 / 4;                                    // 128 float4 per row
    const float4* W4 = reinterpret_cast<const float4*>(W);
    int tid  = threadIdx.x;
    int gw   = (blockIdx.x * blockDim.x + tid) >> 5;           // one warp per sample
    int lane = tid & 31;

    // Cooperative preload of hot rows (ALL threads participate before any exit).
    #pragma unroll
    for (int i = 0; i < HOTK; ++i)
        sW[i * 128 + tid] = W4[i * 128 + tid];
    __syncthreads();

    if (gw >= B) return;

    // Embedding row in registers: 4x float4 per lane, coalesced.
    const float4* e4 = reinterpret_cast<const float4*>(emb) + (size_t)gw * D4;
    float4 e0 = e4[lane +  0];
    float4 e1 = e4[lane + 32];
    float4 e2 = e4[lane + 64];
    float4 e3 = e4[lane + 96];

    int t = __ldg(target + gw);
    const int* nrow = path_nodes + (size_t)t * L;
    const int* drow = path_dirs  + (size_t)t * L;

    // Coalesced per-lane node/dir loads: lane l owns path step l.
    int my_node = (lane < L) ? __ldg(nrow + lane) : 0;
    int my_dir  = (lane < L) ? __ldg(drow + lane) : 0;

    // Active mask via shfl_up + ballot (root id 0 terminates the path).
    int prev = __shfl_up_sync(FULLMASK, my_node, 1);
    bool act = (lane < L) && (lane == 0 || prev != 0);
    unsigned am = __ballot_sync(FULLMASK, act);

    // Chunk A: steps 0..15. Lane l gets dot of step (l & 15).
    float sA = hs_dot16_hot(W4, sW, am, 0, my_node, lane, e0, e1, e2, e3);

    // Chunk B: steps 16..31 — warp-uniform skip when the path is short.
    float sB = 0.0f;
    if (am >> 16)
        sB = hs_dot16_hot(W4, sW, am, 16, my_node, lane, e0, e1, e2, e3);

    // Epilogue: lane l holds step l's dot (sA for l<16, sB for l>=16 since
    // base + (l & 15) == l). One bias gather + one sigmoid per active lane.
    float dotv = (lane < 16) ? sA : sB;
    float f = 1.0f;
    if (act) {
        float sc = dotv + __ldg(bias + my_node);
        float sg = my_dir ? sc : -sc;
        f = __fdividef(1.0f, 1.0f + __expf(-sg));
    }
    #pragma unroll
    for (int o = 16; o >= 1; o >>= 1)
        f *= __shfl_xor_sync(FULLMASK, f, o);

    if (lane == 0) out[gw] = f;
}

// Generic fallback (any D, any L) — shape safety, not the hot path.
__global__ __launch_bounds__(256)
void hs_generic_kernel(const float* __restrict__ emb,
                       const float* __restrict__ W,
                       const float* __restrict__ bias,
                       const int*   __restrict__ target,
                       const int*   __restrict__ path_nodes,
                       const int*   __restrict__ path_dirs,
                       float*       __restrict__ out,
                       int B, int D, int L)
{
    int gw   = (blockIdx.x * blockDim.x + threadIdx.x) >> 5;
    int lane = threadIdx.x & 31;
    if (gw >= B) return;

    const float* e = emb + (size_t)gw * D;
    int t = __ldg(target + gw);
    const int* nrow = path_nodes + (size_t)t * L;
    const int* drow = path_dirs  + (size_t)t * L;

    float prod = 1.0f;
    for (int l = 0; l < L; ++l) {
        int node = __ldg(nrow + l);
        int dir  = __ldg(drow + l);
        const float* w = W + (size_t)node * D;
        float acc = 0.0f;
        for (int d = lane; d < D; d += 32)
            acc = fmaf(e[d], w[d], acc);
        #pragma unroll
        for (int off = 16; off > 0; off >>= 1)
            acc += __shfl_xor_sync(FULLMASK, acc, off);
        float s  = acc + __ldg(bias + node);
        float sg = dir ? s : -s;
        prod *= __fdividef(1.0f, 1.0f + __expf(-sg));
        if (node == 0) break;
    }
    if (lane == 0) out[gw] = prod;
}

extern "C" void kernel_launch(void* const* d_in, const int* in_sizes, int n_in,
                              void* d_out, int out_size)
{
    const float* emb    = (const float*)d_in[0];   // [B, D] f32
    const float* W      = (const float*)d_in[1];   // [V-1, D] f32
    const float* bias   = (const float*)d_in[2];   // [V-1] f32
    const int*   target = (const int*)  d_in[3];   // [B] i32
    const int*   nodes  = (const int*)  d_in[4];   // [V, L] i32
    const int*   dirs   = (const int*)  d_in[5];   // [V, L] i32
    // d_in[6] = path_mask: unused (validity derived from node==0 sentinel)

    int B = in_sizes[3];
    int D = in_sizes[0] / B;
    int V = in_sizes[2] + 1;
    int L = in_sizes[4] / V;
    float* out = (float*)d_out;

    if (D == 512 && L <= MAXL && V - 1 >= HOTK) {
        int threads = 128;                         // 4 warps = 4 samples per block
        int blocks  = (B * 32 + threads - 1) / threads;
        hs512_v12_kernel<<<blocks, threads>>>(emb, W, bias, target, nodes, dirs, out, B, L);
    } else {
        int threads = 256;
        int blocks  = (B * 32 + threads - 1) / threads;
        hs_generic_kernel<<<blocks, threads>>>(emb, W, bias, target, nodes, dirs, out, B, D, L);
    }
}

// round 13
// speedup vs baseline: 1.3409x; 1.1604x over previous
#include <cuda_runtime.h>
#include <cuda_bf16.h>

#define FULLMASK 0xffffffffu
#define MAXL 32

// HierarchicalSoftmax. One warp per sample; two 16-step chunks, each a batched
// W-row load burst + 16-acc register butterfly that transposes step-sums onto
// lanes (lane l ends with the dot product of step l).
//
// v13: inner products computed with Blackwell packed fp32 FMA (fma.rn.f32x2 ->
// FFMA2, rt=1/SMSP vs 2 for scalar FFMA): 8 packed FMAs replace 16 scalar ones
// per step, cutting the dominant loop body's issue-slot count ~30%. Memory
// behavior identical to the 12.74us v9 champion.
//
// Path validity from data: Huffman root id 0 is the LAST valid entry of every
// path; padding is also 0 -> active[l] = (l<L) && (l==0 || node[l-1]!=0).

typedef unsigned long long u64;

__device__ __forceinline__ u64 ffma2(u64 a, u64 b, u64 c)
{
    u64 d;
    asm("fma.rn.f32x2 %0, %1, %2, %3;" : "=l"(d) : "l"(a), "l"(b), "l"(c));
    return d;
}

__device__ __forceinline__ float f32x2_hsum(u64 p)
{
    float lo, hi;
    asm("mov.b64 {%0, %1}, %2;" : "=f"(lo), "=f"(hi) : "l"(p));
    return lo + hi;
}

// Dot of 16 path steps; every lane loads its 16 floats of each step's W row as
// two ulonglong2 pairs (same LDG.128s as before) and accumulates in f32x2.
__device__ __forceinline__ float hs_dot16p(const ulonglong2* __restrict__ Wv,
                                           unsigned am, int base, int my_node,
                                           int lane,
                                           ulonglong2 ea, ulonglong2 eb,
                                           ulonglong2 ec, ulonglong2 ed)
{
    float acc[16];
    #pragma unroll
    for (int i = 0; i < 16; ++i) {
        float s = 0.0f;
        if ((am >> (base + i)) & 1u) {               // warp-uniform (prefix mask)
            int node = __shfl_sync(FULLMASK, my_node, base + i);
            const ulonglong2* w = Wv + (size_t)node * 128;
            ulonglong2 w0 = w[lane +  0];
            ulonglong2 w1 = w[lane + 32];
            ulonglong2 w2 = w[lane + 64];
            ulonglong2 w3 = w[lane + 96];
            u64 p = ffma2(ea.x, w0.x, 0ULL);         // {0,0} bits == 0ULL
            p = ffma2(ea.y, w0.y, p);
            p = ffma2(eb.x, w1.x, p);
            p = ffma2(eb.y, w1.y, p);
            p = ffma2(ec.x, w2.x, p);
            p = ffma2(ec.y, w2.y, p);
            p = ffma2(ed.x, w3.x, p);
            p = ffma2(ed.y, w3.y, p);
            s = f32x2_hsum(p);
        }
        acc[i] = s;
    }
    // Butterfly: strides 8..1 reduce within each 16-lane half; afterwards lane l
    // holds the half-sum of step (l & 15). Stride-16 combine -> full dot product.
    #pragma unroll
    for (int h = 8; h >= 1; h >>= 1) {
        #pragma unroll
        for (int i = 0; i < h; ++i) {
            float v = acc[i], w = acc[i + h];
            float give = (lane & h) ? v : w;
            float got  = __shfl_xor_sync(FULLMASK, give, h);
            acc[i] = ((lane & h) ? w : v) + got;
        }
    }
    return acc[0] + __shfl_xor_sync(FULLMASK, acc[0], 16);
}

__global__ __launch_bounds__(128, 7)
void hs512_v13_kernel(const float* __restrict__ emb,
                      const float* __restrict__ W,
                      const float* __restrict__ bias,
                      const int*   __restrict__ target,
                      const int*   __restrict__ path_nodes,
                      const int*   __restrict__ path_dirs,
                      float*       __restrict__ out,
                      int B, int L)
{
    const int D16 = 512 / 4;                                   // 128 16B chunks/row
    int gw   = (blockIdx.x * blockDim.x + threadIdx.x) >> 5;   // one warp per sample
    int lane = threadIdx.x & 31;
    if (gw >= B) return;

    // Embedding row in registers as packed f32x2 pairs: 4x 16B per lane.
    const ulonglong2* ev = reinterpret_cast<const ulonglong2*>(emb) + (size_t)gw * D16;
    ulonglong2 ea = ev[lane +  0];
    ulonglong2 eb = ev[lane + 32];
    ulonglong2 ec = ev[lane + 64];
    ulonglong2 ed = ev[lane + 96];

    int t = __ldg(target + gw);
    const int* nrow = path_nodes + (size_t)t * L;
    const int* drow = path_dirs  + (size_t)t * L;

    // Coalesced per-lane node/dir loads: lane l owns path step l.
    int my_node = (lane < L) ? __ldg(nrow + lane) : 0;
    int my_dir  = (lane < L) ? __ldg(drow + lane) : 0;

    // Active mask via shfl_up + ballot (root id 0 terminates the path).
    int prev = __shfl_up_sync(FULLMASK, my_node, 1);
    bool act = (lane < L) && (lane == 0 || prev != 0);
    unsigned am = __ballot_sync(FULLMASK, act);

    const ulonglong2* Wv = reinterpret_cast<const ulonglong2*>(W);

    // Chunk A: steps 0..15. Lane l gets dot of step (l & 15).
    float sA = hs_dot16p(Wv, am, 0, my_node, lane, ea, eb, ec, ed);

    // Chunk B: steps 16..31 — warp-uniform skip when the path is short.
    float sB = 0.0f;
    if (am >> 16)
        sB = hs_dot16p(Wv, am, 16, my_node, lane, ea, eb, ec, ed);

    // Epilogue: lane l holds step l's dot (sA for l<16, sB for l>=16 since
    // base + (l & 15) == l). One bias gather + one sigmoid per active lane.
    float dotv = (lane < 16) ? sA : sB;
    float f = 1.0f;
    if (act) {
        float sc = dotv + __ldg(bias + my_node);
        float sg = my_dir ? sc : -sc;
        f = __fdividef(1.0f, 1.0f + __expf(-sg));
    }
    #pragma unroll
    for (int o = 16; o >= 1; o >>= 1)
        f *= __shfl_xor_sync(FULLMASK, f, o);

    if (lane == 0) out[gw] = f;
}

// Generic fallback (any D, any L) — shape safety, not the hot path.
__global__ __launch_bounds__(256)
void hs_generic_kernel(const float* __restrict__ emb,
                       const float* __restrict__ W,
                       const float* __restrict__ bias,
                       const int*   __restrict__ target,
                       const int*   __restrict__ path_nodes,
                       const int*   __restrict__ path_dirs,
                       float*       __restrict__ out,
                       int B, int D, int L)
{
    int gw   = (blockIdx.x * blockDim.x + threadIdx.x) >> 5;
    int lane = threadIdx.x & 31;
    if (gw >= B) return;

    const float* e = emb + (size_t)gw * D;
    int t = __ldg(target + gw);
    const int* nrow = path_nodes + (size_t)t * L;
    const int* drow = path_dirs  + (size_t)t * L;

    float prod = 1.0f;
    for (int l = 0; l < L; ++l) {
        int node = __ldg(nrow + l);
        int dir  = __ldg(drow + l);
        const float* w = W + (size_t)node * D;
        float acc = 0.0f;
        for (int d = lane; d < D; d += 32)
            acc = fmaf(e[d], w[d], acc);
        #pragma unroll
        for (int off = 16; off > 0; off >>= 1)
            acc += __shfl_xor_sync(FULLMASK, acc, off);
        float s  = acc + __ldg(bias + node);
        float sg = dir ? s : -s;
        prod *= __fdividef(1.0f, 1.0f + __expf(-sg));
        if (node == 0) break;
    }
    if (lane == 0) out[gw] = prod;
}

extern "C" void kernel_launch(void* const* d_in, const int* in_sizes, int n_in,
                              void* d_out, int out_size)
{
    const float* emb    = (const float*)d_in[0];   // [B, D] f32
    const float* W      = (const float*)d_in[1];   // [V-1, D] f32
    const float* bias   = (const float*)d_in[2];   // [V-1] f32
    const int*   target = (const int*)  d_in[3];   // [B] i32
    const int*   nodes  = (const int*)  d_in[4];   // [V, L] i32
    const int*   dirs   = (const int*)  d_in[5];   // [V, L] i32
    // d_in[6] = path_mask: unused (validity derived from node==0 sentinel)

    int B = in_sizes[3];
    int D = in_sizes[0] / B;
    int V = in_sizes[2] + 1;
    int L = in_sizes[4] / V;
    float* out = (float*)d_out;

    if (D == 512 && L <= MAXL) {
        int threads = 128;                         // 4 warps = 4 samples per block
        int blocks  = (B * 32 + threads - 1) / threads;
        hs512_v13_kernel<<<blocks, threads>>>(emb, W, bias, target, nodes, dirs, out, B, L);
    } else {
        int threads = 256;
        int blocks  = (B * 32 + threads - 1) / threads;
        hs_generic_kernel<<<blocks, threads>>>(emb, W, bias, target, nodes, dirs, out, B, D, L);
    }
}